// round 15
// baseline (speedup 1.0000x reference)
#include <cuda_runtime.h>
#include <cstdint>

#define B     8
#define A     49104
#define C     20
#define M     32
#define NANN  16
#define A5    (A * 5)                     // float4 columns per batch plane
#define GA    384                         // assign blocks (128 anchors each)
#define GC    296                         // persistent cls blocks (2/SM)
#define BLKC  128                         // columns per segment
#define THR   256                         // k_cls threads: (col, batch-half)
#define NSTG  3
#define NSEG  ((A5 + BLKC - 1) / BLKC)    // 1919 segments (last has 16 cols)
#define LN2F  0.6931471805599453f

#define STAGE_F4   (16 * BLKC)            // float4 per stage (8 e + 8 c planes)
#define SMEM_BYTES (NSTG * STAGE_F4 * 16)

// ---- scratch (device globals; every slot written every call) ----
__device__ unsigned char g_aflags[A];     // per-anchor byte: bit b = assigned
__device__ float g_pr[B][GA];
__device__ int   g_pn[B][GA];
__device__ float g_pc[B][GC];
__device__ int   g_count = 0;             // last cls block resets -> replay-invariant

// ================= Kernel A: assignment (warp = batch) =================
__global__ void __launch_bounds__(256) k_assign(
    const float* __restrict__ regressions,  // [B,A,4]
    const float* __restrict__ anchors,      // [1,A,4]
    const float* __restrict__ ema_classes,  // [B,M]
    const float* __restrict__ ema_bboxes,   // [B,M,4]
    const int*   __restrict__ ema_counts,   // [B]
    const float* __restrict__ annotations)  // [B,N,5]
{
    __shared__ float4   s_cbox[B][M];
    __shared__ float    s_carea[B][M];
    __shared__ unsigned s_abits[B][4];
    __shared__ float    s_rw[B];
    __shared__ int      s_nw[B];

    const int tid  = threadIdx.x;
    const int lane = tid & 31;
    const int b    = tid >> 5;             // warp = batch

    {
        // -- compact kept boxes (order-preserving => first-argmax semantics)
        float4 bb4 = ((const float4*)ema_bboxes)[b * M + lane];
        bool vld = lane < ema_counts[b];
        float cl = ema_classes[b * M + lane];
        bool mem = false;
        #pragma unroll
        for (int n = 0; n < NANN; n++)
            mem |= (cl == annotations[(b * NANN + n) * 5 + 4]);
        unsigned msk = __ballot_sync(0xffffffffu, vld && mem);
        int p = __popc(msk & ((1u << lane) - 1u));
        if ((msk >> lane) & 1u) {
            s_cbox[b][p]  = bb4;
            s_carea[b][p] = (bb4.z - bb4.x) * (bb4.w - bb4.y);
        }
        const int cnt = __popc(msk);        // uniform in warp
        __syncwarp();

        float racc = 0.f;
        int   np   = 0;
        #pragma unroll
        for (int h = 0; h < 4; h++) {
            const int a = blockIdx.x * 128 + h * 32 + lane;
            const bool valid = (a < A);
            const float4 an = ((const float4*)anchors)[valid ? a : 0];
            const float aw = an.z - an.x, ah = an.w - an.y;
            const float acx = an.x + 0.5f * aw, acy = an.y + 0.5f * ah;
            const float area_a = aw * ah;

            float bI = -1.f, bU = 1.f;
            int   bi = 0;
            for (int m = 0; m < cnt; m++) {
                float4 bx = s_cbox[b][m];   // LDS broadcast
                float iw = fminf(an.z, bx.z) - fmaxf(an.x, bx.x);
                float ih = fminf(an.w, bx.w) - fmaxf(an.y, bx.y);
                iw = fmaxf(iw, 0.f);
                ih = fmaxf(ih, 0.f);
                float inter = iw * ih;
                float u = fmaxf(area_a + s_carea[b][m] - inter, 1e-8f);
                bool better = inter * bU > bI * u;   // iou > best (u,bU > 0)
                bi = better ? m : bi;
                bI = better ? inter : bI;
                bU = better ? u : bU;
            }
            const bool has = (cnt > 0) && valid;
            const bool pos = has && (bI >= 0.5f * bU);
            const bool assigned = has && ((bI < 0.4f * bU) || (bI >= 0.5f * bU));

            unsigned ab = __ballot_sync(0xffffffffu, assigned);
            unsigned pb = __ballot_sync(0xffffffffu, pos);
            if (lane == 0) s_abits[b][h] = ab;
            np += __popc(pb);

            if (pos) {
                float4 r = ((const float4*)regressions)[(size_t)b * A + a];
                float4 g = s_cbox[b][bi];
                float gw = g.z - g.x, gh = g.w - g.y;
                float gcx = g.x + 0.5f * gw, gcy = g.y + 0.5f * gh;
                gw = fmaxf(gw, 1.f);
                gh = fmaxf(gh, 1.f);
                float dx = (gcx - acx) / aw / 0.1f;
                float dy = (gcy - acy) / ah / 0.1f;
                float dw = __logf(gw / aw) / 0.2f;
                float dh = __logf(gh / ah) / 0.2f;
                float d;
                d = fabsf(dx - r.x); racc += (d <= 1.f/9.f) ? 4.5f*d*d : d - 0.5f/9.f;
                d = fabsf(dy - r.y); racc += (d <= 1.f/9.f) ? 4.5f*d*d : d - 0.5f/9.f;
                d = fabsf(dw - r.z); racc += (d <= 1.f/9.f) ? 4.5f*d*d : d - 0.5f/9.f;
                d = fabsf(dh - r.w); racc += (d <= 1.f/9.f) ? 4.5f*d*d : d - 0.5f/9.f;
            }
        }
        #pragma unroll
        for (int o = 16; o; o >>= 1) racc += __shfl_down_sync(0xffffffffu, racc, o);
        if (lane == 0) { s_rw[b] = racc; s_nw[b] = np; }
    }
    __syncthreads();

    // -- transpose bitmasks into per-anchor flag bytes
    if (tid < 128) {
        const int a = blockIdx.x * 128 + tid;
        if (a < A) {
            const int w = tid >> 5, sft = tid & 31;
            unsigned byte = 0;
            #pragma unroll
            for (int bb = 0; bb < 8; bb++)
                byte |= ((s_abits[bb][w] >> sft) & 1u) << bb;
            g_aflags[a] = (unsigned char)byte;
        }
    }
    if (tid < 8) {
        g_pr[tid][blockIdx.x] = s_rw[tid];
        g_pn[tid][blockIdx.x] = s_nw[tid];
    }
}

// ======== Kernel B: cls, bulk-copy staged, thread = (col, batch-half) ========

__device__ __forceinline__ unsigned sm32(const void* p) {
    return (unsigned)__cvta_generic_to_shared(p);
}

__device__ __forceinline__ void mbar_wait(unsigned mbar, int phase) {
    asm volatile(
        "{\n\t.reg .pred P;\n\t"
        "WAIT_%=:\n\t"
        "mbarrier.try_wait.parity.acquire.cta.shared::cta.b64 P, [%0], %1, 0x989680;\n\t"
        "@P bra.uni DONE_%=;\n\t"
        "bra.uni WAIT_%=;\n\t"
        "DONE_%=:\n\t}"
        :: "r"(mbar), "r"(phase) : "memory");
}

__global__ void __launch_bounds__(THR, 2) k_cls(
    const float* __restrict__ cls_in,   // [B,A,C]
    const float* __restrict__ ema_in,   // [B,A,C]
    float* __restrict__ out)
{
    extern __shared__ float4 s_buf[];                 // [NSTG][16][BLKC]
    __shared__ __align__(8) unsigned long long s_mbar[NSTG];
    __shared__ float s_c[8][8];
    __shared__ bool  s_last;

    const int tid  = threadIdx.x;
    const int lane = tid & 31;
    const int wrp  = tid >> 5;                        // 0..7
    const int half = tid & 1;                         // batch-half
    const int lcol = tid >> 1;                        // local column 0..127

    if (tid == 0) {
        #pragma unroll
        for (int s = 0; s < NSTG; s++)
            asm volatile("mbarrier.init.shared.b64 [%0], 1;"
                         :: "r"(sm32(&s_mbar[s])) : "memory");
    }
    __syncthreads();

    const char* eb = (const char*)ema_in;
    const char* cb = (const char*)cls_in;

    auto issue = [&](int stage, int seg) {
        int cols = min(BLKC, A5 - seg * BLKC);
        unsigned bytes = (unsigned)cols * 16u;
        unsigned mb = sm32(&s_mbar[stage]);
        asm volatile("mbarrier.arrive.expect_tx.shared.b64 _, [%0], %1;"
                     :: "r"(mb), "r"(bytes * 16u) : "memory");
        size_t off = (size_t)seg * BLKC * 16;
        unsigned dst = sm32(&s_buf[stage * STAGE_F4]);
        #pragma unroll
        for (int b = 0; b < 8; b++) {
            asm volatile(
                "cp.async.bulk.shared::cluster.global.mbarrier::complete_tx::bytes [%0], [%1], %2, [%3];"
                :: "r"(dst + b * (BLKC * 16)),
                   "l"(eb + (size_t)b * A5 * 16 + off), "r"(bytes), "r"(mb) : "memory");
        }
        #pragma unroll
        for (int b = 0; b < 8; b++) {
            asm volatile(
                "cp.async.bulk.shared::cluster.global.mbarrier::complete_tx::bytes [%0], [%1], %2, [%3];"
                :: "r"(dst + (8 + b) * (BLKC * 16)),
                   "l"(cb + (size_t)b * A5 * 16 + off), "r"(bytes), "r"(mb) : "memory");
        }
    };

    float cacc[4] = {0.f, 0.f, 0.f, 0.f};

    const int s0 = blockIdx.x;
    if (tid == 0) {
        #pragma unroll
        for (int k = 0; k < NSTG; k++)
            if (s0 + k * GC < NSEG) issue(k, s0 + k * GC);
    }

    int it = 0;
    for (int s = s0; s < NSEG; s += GC, it++) {
        const int stage = it % NSTG;
        const int ph    = (it / NSTG) & 1;
        mbar_wait(sm32(&s_mbar[stage]), ph);

        const int col = s * BLKC + lcol;
        const float4* sp = &s_buf[stage * STAGE_F4];

        // own 4 e planes (b = half*4 + j)
        float4 e0 = sp[(half * 4 + 0) * BLKC + lcol];
        float4 e1 = sp[(half * 4 + 1) * BLKC + lcol];
        float4 e2 = sp[(half * 4 + 2) * BLKC + lcol];
        float4 e3 = sp[(half * 4 + 3) * BLKC + lcol];

        // alpha: own-half sum + partner via xor-1 (pairs share a column)
        float4 S;
        S.x = (e0.x + e1.x) + (e2.x + e3.x);
        S.y = (e0.y + e1.y) + (e2.y + e3.y);
        S.z = (e0.z + e1.z) + (e2.z + e3.z);
        S.w = (e0.w + e1.w) + (e2.w + e3.w);
        S.x += __shfl_xor_sync(0xffffffffu, S.x, 1);
        S.y += __shfl_xor_sync(0xffffffffu, S.y, 1);
        S.z += __shfl_xor_sync(0xffffffffu, S.z, 1);
        S.w += __shfl_xor_sync(0xffffffffu, S.w, 1);
        const float ax = 0.4f + 0.9f * S.x;           // LN2 folded to epilogue
        const float ay = 0.4f + 0.9f * S.y;
        const float az = 0.4f + 0.9f * S.z;
        const float aw = 0.4f + 0.9f * S.w;

        const unsigned flags = (col < A5) ? (unsigned)g_aflags[col / 5] : 0u;

        #pragma unroll
        for (int j = 0; j < 4; j++) {
            float4 e = (j == 0) ? e0 : (j == 1) ? e1 : (j == 2) ? e2 : e3;
            float4 c = sp[(8 + half * 4 + j) * BLKC + lcol];
            float t = 0.f;
            {
                float ec = fminf(fmaxf(e.x, 1e-4f), 1.f - 1e-4f);
                float cc = fminf(fmaxf(c.x, 1e-4f), 1.f - 1e-4f);
                float l2c = __log2f(cc), l2d = __log2f(1.f - cc);
                float bce2 = -(l2d + ec * (l2c - l2d));
                float d = ec - cc;
                t += (ax * (d * d)) * bce2;
            }
            {
                float ec = fminf(fmaxf(e.y, 1e-4f), 1.f - 1e-4f);
                float cc = fminf(fmaxf(c.y, 1e-4f), 1.f - 1e-4f);
                float l2c = __log2f(cc), l2d = __log2f(1.f - cc);
                float bce2 = -(l2d + ec * (l2c - l2d));
                float d = ec - cc;
                t += (ay * (d * d)) * bce2;
            }
            {
                float ec = fminf(fmaxf(e.z, 1e-4f), 1.f - 1e-4f);
                float cc = fminf(fmaxf(c.z, 1e-4f), 1.f - 1e-4f);
                float l2c = __log2f(cc), l2d = __log2f(1.f - cc);
                float bce2 = -(l2d + ec * (l2c - l2d));
                float d = ec - cc;
                t += (az * (d * d)) * bce2;
            }
            {
                float ec = fminf(fmaxf(e.w, 1e-4f), 1.f - 1e-4f);
                float cc = fminf(fmaxf(c.w, 1e-4f), 1.f - 1e-4f);
                float l2c = __log2f(cc), l2d = __log2f(1.f - cc);
                float bce2 = -(l2d + ec * (l2c - l2d));
                float d = ec - cc;
                t += (aw * (d * d)) * bce2;
            }
            if ((flags >> (half * 4 + j)) & 1u) cacc[j] += t;   // predicated add
        }

        __syncthreads();                              // stage fully consumed
        int snext = s + NSTG * GC;
        if (tid == 0 && snext < NSEG) issue(stage, snext);
    }

    // epilogue: reduce over same-half lanes (xor 2,4,8,16)
    #pragma unroll
    for (int j = 0; j < 4; j++) {
        float v = cacc[j];
        #pragma unroll
        for (int o = 2; o <= 16; o <<= 1) v += __shfl_xor_sync(0xffffffffu, v, o);
        cacc[j] = v;
    }
    if (lane < 2) {
        #pragma unroll
        for (int j = 0; j < 4; j++) s_c[wrp][lane * 4 + j] = cacc[j];
    }
    __syncthreads();
    if (tid < 8) {
        float cs = 0.f;
        #pragma unroll
        for (int w = 0; w < 8; w++) cs += s_c[w][tid];
        g_pc[tid][blockIdx.x] = cs;
        __threadfence();
    }
    __syncthreads();
    if (tid == 0) s_last = (atomicAdd(&g_count, 1) == GC - 1);
    __syncthreads();
    if (!s_last) return;
    __threadfence();

    // final: warp b reduces batch b over all partials
    if (wrp < 8) {
        const int b = wrp;
        float cs = 0.f, rs = 0.f;
        int   ns = 0;
        for (int i = lane; i < GC; i += 32) cs += g_pc[b][i];
        for (int i = lane; i < GA; i += 32) { rs += g_pr[b][i]; ns += g_pn[b][i]; }
        #pragma unroll
        for (int o = 16; o; o >>= 1) {
            cs += __shfl_down_sync(0xffffffffu, cs, o);
            rs += __shfl_down_sync(0xffffffffu, rs, o);
            ns += __shfl_down_sync(0xffffffffu, ns, o);
        }
        if (lane == 0) {
            float npf = (float)ns;
            float mx  = fmaxf(npf, 1.f);
            s_c[0][b] = cs / mx;
            s_c[1][b] = (npf > 0.f) ? rs / (4.f * mx) : 0.f;
        }
    }
    __syncthreads();
    if (tid == 0) {
        float cs = 0.f, rs = 0.f;
        #pragma unroll
        for (int b = 0; b < 8; b++) { cs += s_c[0][b]; rs += s_c[1][b]; }
        out[0] = cs * (0.125f * LN2F);
        out[1] = rs * 0.125f;
        g_count = 0;
    }
}

extern "C" void kernel_launch(void* const* d_in, const int* in_sizes, int n_in,
                              void* d_out, int out_size) {
    const float* classifications     = (const float*)d_in[0];
    const float* regressions         = (const float*)d_in[1];
    const float* anchors             = (const float*)d_in[2];
    const float* ema_classifications = (const float*)d_in[3];
    const float* ema_classes         = (const float*)d_in[4];
    const float* ema_bboxes          = (const float*)d_in[5];
    const int*   ema_counts          = (const int*)d_in[6];
    const float* annotations         = (const float*)d_in[7];

    cudaFuncSetAttribute(k_cls, cudaFuncAttributeMaxDynamicSharedMemorySize, SMEM_BYTES);

    k_assign<<<GA, 256>>>(regressions, anchors, ema_classes,
                          ema_bboxes, ema_counts, annotations);
    k_cls<<<GC, THR, SMEM_BYTES>>>(classifications, ema_classifications, (float*)d_out);
}

// round 16
// speedup vs baseline: 1.2554x; 1.2554x over previous
#include <cuda_runtime.h>
#include <cstdint>

#define B     8
#define A     49104
#define C     20
#define M     32
#define NANN  16
#define A5    (A * 5)                     // float4 columns per batch plane
#define GA    384                         // assign blocks (128 anchors each)
#define GC    296                         // persistent cls blocks (2/SM)
#define BLKC  128                         // k_cls threads (= cols per segment)
#define NSTG  3
#define NSEG  ((A5 + BLKC - 1) / BLKC)    // 1919 segments (last has 16 cols)
#define LN2F  0.6931471805599453f

// ---- scratch (device globals; every slot written every call) ----
__device__ unsigned char g_aflags[A];     // per-anchor byte: bit b = assigned
__device__ float g_pr[B][GA];
__device__ int   g_pn[B][GA];
__device__ float g_pc[B][GC];
__device__ int   g_count = 0;             // last cls block resets -> replay-invariant

// ================= Kernel A: assignment (warp = batch) =================
__global__ void __launch_bounds__(256) k_assign(
    const float* __restrict__ regressions,  // [B,A,4]
    const float* __restrict__ anchors,      // [1,A,4]
    const float* __restrict__ ema_classes,  // [B,M]
    const float* __restrict__ ema_bboxes,   // [B,M,4]
    const int*   __restrict__ ema_counts,   // [B]
    const float* __restrict__ annotations)  // [B,N,5]
{
    __shared__ float4   s_cbox[B][M];
    __shared__ float    s_carea[B][M];
    __shared__ unsigned s_abits[B][4];
    __shared__ float    s_rw[B];
    __shared__ int      s_nw[B];

    const int tid  = threadIdx.x;
    const int lane = tid & 31;
    const int b    = tid >> 5;             // warp = batch

    {
        // -- compact kept boxes (order-preserving => first-argmax semantics)
        float4 bb4 = ((const float4*)ema_bboxes)[b * M + lane];
        bool vld = lane < ema_counts[b];
        float cl = ema_classes[b * M + lane];
        bool mem = false;
        #pragma unroll
        for (int n = 0; n < NANN; n++)
            mem |= (cl == annotations[(b * NANN + n) * 5 + 4]);
        unsigned msk = __ballot_sync(0xffffffffu, vld && mem);
        int p = __popc(msk & ((1u << lane) - 1u));
        if ((msk >> lane) & 1u) {
            s_cbox[b][p]  = bb4;
            s_carea[b][p] = (bb4.z - bb4.x) * (bb4.w - bb4.y);
        }
        const int cnt = __popc(msk);        // uniform in warp
        __syncwarp();

        float racc = 0.f;
        int   np   = 0;
        #pragma unroll
        for (int h = 0; h < 4; h++) {
            const int a = blockIdx.x * 128 + h * 32 + lane;
            const bool valid = (a < A);
            const float4 an = ((const float4*)anchors)[valid ? a : 0];
            const float aw = an.z - an.x, ah = an.w - an.y;
            const float acx = an.x + 0.5f * aw, acy = an.y + 0.5f * ah;
            const float area_a = aw * ah;

            float bI = -1.f, bU = 1.f;
            int   bi = 0;
            for (int m = 0; m < cnt; m++) {
                float4 bx = s_cbox[b][m];   // LDS broadcast
                float iw = fminf(an.z, bx.z) - fmaxf(an.x, bx.x);
                float ih = fminf(an.w, bx.w) - fmaxf(an.y, bx.y);
                iw = fmaxf(iw, 0.f);
                ih = fmaxf(ih, 0.f);
                float inter = iw * ih;
                float u = fmaxf(area_a + s_carea[b][m] - inter, 1e-8f);
                bool better = inter * bU > bI * u;   // iou > best (u,bU > 0)
                bi = better ? m : bi;
                bI = better ? inter : bI;
                bU = better ? u : bU;
            }
            const bool has = (cnt > 0) && valid;
            const bool pos = has && (bI >= 0.5f * bU);
            const bool assigned = has && ((bI < 0.4f * bU) || (bI >= 0.5f * bU));

            unsigned ab = __ballot_sync(0xffffffffu, assigned);
            unsigned pb = __ballot_sync(0xffffffffu, pos);
            if (lane == 0) s_abits[b][h] = ab;
            np += __popc(pb);

            if (pos) {
                float4 r = ((const float4*)regressions)[(size_t)b * A + a];
                float4 g = s_cbox[b][bi];
                float gw = g.z - g.x, gh = g.w - g.y;
                float gcx = g.x + 0.5f * gw, gcy = g.y + 0.5f * gh;
                gw = fmaxf(gw, 1.f);
                gh = fmaxf(gh, 1.f);
                float dx = (gcx - acx) / aw / 0.1f;
                float dy = (gcy - acy) / ah / 0.1f;
                float dw = __logf(gw / aw) / 0.2f;
                float dh = __logf(gh / ah) / 0.2f;
                float d;
                d = fabsf(dx - r.x); racc += (d <= 1.f/9.f) ? 4.5f*d*d : d - 0.5f/9.f;
                d = fabsf(dy - r.y); racc += (d <= 1.f/9.f) ? 4.5f*d*d : d - 0.5f/9.f;
                d = fabsf(dw - r.z); racc += (d <= 1.f/9.f) ? 4.5f*d*d : d - 0.5f/9.f;
                d = fabsf(dh - r.w); racc += (d <= 1.f/9.f) ? 4.5f*d*d : d - 0.5f/9.f;
            }
        }
        #pragma unroll
        for (int o = 16; o; o >>= 1) racc += __shfl_down_sync(0xffffffffu, racc, o);
        if (lane == 0) { s_rw[b] = racc; s_nw[b] = np; }
    }
    __syncthreads();

    // -- transpose bitmasks into per-anchor flag bytes
    if (tid < 128) {
        const int a = blockIdx.x * 128 + tid;
        if (a < A) {
            const int w = tid >> 5, sft = tid & 31;
            unsigned byte = 0;
            #pragma unroll
            for (int bb = 0; bb < 8; bb++)
                byte |= ((s_abits[bb][w] >> sft) & 1u) << bb;
            g_aflags[a] = (unsigned char)byte;
        }
    }
    if (tid < 8) {
        g_pr[tid][blockIdx.x] = s_rw[tid];
        g_pn[tid][blockIdx.x] = s_nw[tid];
    }
}

// ======== Kernel B: cls via cp.async.bulk TRIPLE-buffered smem staging ========
// R12 structure verbatim; only NSTG 2 -> 3.

#define STAGE_F4   (16 * BLKC)            // float4 slots per stage (8 e + 8 c planes)
#define SMEM_BYTES (NSTG * STAGE_F4 * 16 + 64)

__device__ __forceinline__ unsigned sm32(const void* p) {
    return (unsigned)__cvta_generic_to_shared(p);
}

__device__ __forceinline__ void mbar_wait(unsigned mbar, int phase) {
    asm volatile(
        "{\n\t.reg .pred P;\n\t"
        "WAIT_%=:\n\t"
        "mbarrier.try_wait.parity.acquire.cta.shared::cta.b64 P, [%0], %1, 0x989680;\n\t"
        "@P bra.uni DONE_%=;\n\t"
        "bra.uni WAIT_%=;\n\t"
        "DONE_%=:\n\t}"
        :: "r"(mbar), "r"(phase) : "memory");
}

__global__ void __launch_bounds__(BLKC, 2) k_cls(
    const float* __restrict__ cls_in,   // [B,A,C]
    const float* __restrict__ ema_in,   // [B,A,C]
    float* __restrict__ out)
{
    extern __shared__ float4 s_buf[];                 // [NSTG][16][BLKC]
    __shared__ __align__(8) unsigned long long s_mbar[NSTG];
    __shared__ float s_c[4][8];
    __shared__ bool  s_last;

    const int tid  = threadIdx.x;
    const int lane = tid & 31;
    const int wrp  = tid >> 5;                        // 0..3

    if (tid == 0) {
        #pragma unroll
        for (int s = 0; s < NSTG; s++)
            asm volatile("mbarrier.init.shared.b64 [%0], 1;"
                         :: "r"(sm32(&s_mbar[s])) : "memory");
    }
    __syncthreads();

    const char* eb = (const char*)ema_in;
    const char* cb = (const char*)cls_in;

    // issue all 16 plane copies of one segment into a stage
    auto issue = [&](int stage, int seg) {
        int cols = min(BLKC, A5 - seg * BLKC);
        unsigned bytes = (unsigned)cols * 16u;
        unsigned mb = sm32(&s_mbar[stage]);
        asm volatile("mbarrier.arrive.expect_tx.shared.b64 _, [%0], %1;"
                     :: "r"(mb), "r"(bytes * 16u) : "memory");
        size_t off = (size_t)seg * BLKC * 16;
        unsigned dst = sm32(&s_buf[stage * STAGE_F4]);
        #pragma unroll
        for (int b = 0; b < 8; b++) {
            asm volatile(
                "cp.async.bulk.shared::cluster.global.mbarrier::complete_tx::bytes [%0], [%1], %2, [%3];"
                :: "r"(dst + b * (BLKC * 16)),
                   "l"(eb + (size_t)b * A5 * 16 + off), "r"(bytes), "r"(mb) : "memory");
        }
        #pragma unroll
        for (int b = 0; b < 8; b++) {
            asm volatile(
                "cp.async.bulk.shared::cluster.global.mbarrier::complete_tx::bytes [%0], [%1], %2, [%3];"
                :: "r"(dst + (8 + b) * (BLKC * 16)),
                   "l"(cb + (size_t)b * A5 * 16 + off), "r"(bytes), "r"(mb) : "memory");
        }
    };

    float cacc[8] = {0.f, 0.f, 0.f, 0.f, 0.f, 0.f, 0.f, 0.f};

    const int s0 = blockIdx.x;
    if (tid == 0) {
        #pragma unroll
        for (int k = 0; k < NSTG; k++)
            if (s0 + k * GC < NSEG) issue(k, s0 + k * GC);
    }

    int it = 0;
    for (int s = s0; s < NSEG; s += GC, it++) {
        const int stage = it % NSTG;
        const int ph    = (it / NSTG) & 1;
        mbar_wait(sm32(&s_mbar[stage]), ph);

        const int col = s * BLKC + tid;
        if (col < A5) {
            const float4* sp = &s_buf[stage * STAGE_F4];
            // alpha: sum ema over batches (bug-faithful: unclamped)
            float4 S = sp[tid];
            #pragma unroll
            for (int b = 1; b < 8; b++) {
                float4 e = sp[b * BLKC + tid];
                S.x += e.x; S.y += e.y; S.z += e.z; S.w += e.w;
            }
            const float ax = 0.4f + 0.9f * S.x;       // LN2 folded to epilogue
            const float ay = 0.4f + 0.9f * S.y;
            const float az = 0.4f + 0.9f * S.z;
            const float aw = 0.4f + 0.9f * S.w;
            const unsigned flags = (unsigned)g_aflags[col / 5];

            #pragma unroll
            for (int b = 0; b < 8; b++) {
                float4 e = sp[b * BLKC + tid];
                float4 c = sp[(8 + b) * BLKC + tid];
                float flag = (float)((flags >> b) & 1u);
                float t = 0.f;
                {
                    float ec = fminf(fmaxf(e.x, 1e-4f), 1.f - 1e-4f);
                    float cc = fminf(fmaxf(c.x, 1e-4f), 1.f - 1e-4f);
                    float l2c = __log2f(cc), l2d = __log2f(1.f - cc);
                    float bce2 = -(l2d + ec * (l2c - l2d));
                    float d = ec - cc;
                    t += (ax * (d * d)) * bce2;
                }
                {
                    float ec = fminf(fmaxf(e.y, 1e-4f), 1.f - 1e-4f);
                    float cc = fminf(fmaxf(c.y, 1e-4f), 1.f - 1e-4f);
                    float l2c = __log2f(cc), l2d = __log2f(1.f - cc);
                    float bce2 = -(l2d + ec * (l2c - l2d));
                    float d = ec - cc;
                    t += (ay * (d * d)) * bce2;
                }
                {
                    float ec = fminf(fmaxf(e.z, 1e-4f), 1.f - 1e-4f);
                    float cc = fminf(fmaxf(c.z, 1e-4f), 1.f - 1e-4f);
                    float l2c = __log2f(cc), l2d = __log2f(1.f - cc);
                    float bce2 = -(l2d + ec * (l2c - l2d));
                    float d = ec - cc;
                    t += (az * (d * d)) * bce2;
                }
                {
                    float ec = fminf(fmaxf(e.w, 1e-4f), 1.f - 1e-4f);
                    float cc = fminf(fmaxf(c.w, 1e-4f), 1.f - 1e-4f);
                    float l2c = __log2f(cc), l2d = __log2f(1.f - cc);
                    float bce2 = -(l2d + ec * (l2c - l2d));
                    float d = ec - cc;
                    t += (aw * (d * d)) * bce2;
                }
                cacc[b] += flag * t;
            }
        }
        __syncthreads();                              // all consumed stage
        int snext = s + NSTG * GC;
        if (tid == 0 && snext < NSEG) issue(stage, snext);
    }

    // epilogue: reduce each batch accumulator across warp, then block
    #pragma unroll
    for (int b = 0; b < 8; b++) {
        float v = cacc[b];
        #pragma unroll
        for (int o = 16; o; o >>= 1) v += __shfl_xor_sync(0xffffffffu, v, o);
        cacc[b] = v;
    }
    if (lane == 0) {
        #pragma unroll
        for (int b = 0; b < 8; b++) s_c[wrp][b] = cacc[b];
    }
    __syncthreads();
    if (tid < 8) {
        float cs = s_c[0][tid] + s_c[1][tid] + s_c[2][tid] + s_c[3][tid];
        g_pc[tid][blockIdx.x] = cs;
        __threadfence();
    }
    __syncthreads();
    if (tid == 0) s_last = (atomicAdd(&g_count, 1) == GC - 1);
    __syncthreads();
    if (!s_last) return;
    __threadfence();

    // final: 4 warps, each reduces 2 batches
    for (int b = wrp; b < 8; b += 4) {
        float cs = 0.f, rs = 0.f;
        int   ns = 0;
        for (int i = lane; i < GC; i += 32) cs += g_pc[b][i];
        for (int i = lane; i < GA; i += 32) { rs += g_pr[b][i]; ns += g_pn[b][i]; }
        #pragma unroll
        for (int o = 16; o; o >>= 1) {
            cs += __shfl_down_sync(0xffffffffu, cs, o);
            rs += __shfl_down_sync(0xffffffffu, rs, o);
            ns += __shfl_down_sync(0xffffffffu, ns, o);
        }
        if (lane == 0) {
            float npf = (float)ns;
            float mx  = fmaxf(npf, 1.f);
            s_c[0][b] = cs / mx;
            s_c[1][b] = (npf > 0.f) ? rs / (4.f * mx) : 0.f;
        }
    }
    __syncthreads();
    if (tid == 0) {
        float cs = 0.f, rs = 0.f;
        #pragma unroll
        for (int b = 0; b < 8; b++) { cs += s_c[0][b]; rs += s_c[1][b]; }
        out[0] = cs * (0.125f * LN2F);
        out[1] = rs * 0.125f;
        g_count = 0;
    }
}

extern "C" void kernel_launch(void* const* d_in, const int* in_sizes, int n_in,
                              void* d_out, int out_size) {
    const float* classifications     = (const float*)d_in[0];
    const float* regressions         = (const float*)d_in[1];
    const float* anchors             = (const float*)d_in[2];
    const float* ema_classifications = (const float*)d_in[3];
    const float* ema_classes         = (const float*)d_in[4];
    const float* ema_bboxes          = (const float*)d_in[5];
    const int*   ema_counts          = (const int*)d_in[6];
    const float* annotations         = (const float*)d_in[7];

    cudaFuncSetAttribute(k_cls, cudaFuncAttributeMaxDynamicSharedMemorySize, SMEM_BYTES);

    k_assign<<<GA, 256>>>(regressions, anchors, ema_classes,
                          ema_bboxes, ema_counts, annotations);
    k_cls<<<GC, BLKC, SMEM_BYTES>>>(classifications, ema_classifications, (float*)d_out);
}